// round 15
// baseline (speedup 1.0000x reference)
#include <cuda_runtime.h>
#include <cuda_bf16.h>
#include <cuda_fp16.h>
#include <cstdint>

#define NMAX 100000
#define D 128

typedef unsigned long long ull;

// Scratch (device globals: allocation-free per harness rules)
__device__ __align__(256) uint2 g_x16[(size_t)NMAX * 32];   // fp16 plane of x
__device__ __align__(256) uint2 g_h16[(size_t)NMAX * 32];   // fp16 plane of h (layer-1 out)
__device__ __align__(16)  char  g_W16[131072];              // fp16 weights [layer][kc][n][64]
__device__ int   g_deg[NMAX];
__device__ int   g_off[NMAX + 1];
__device__ int   g_cur[NMAX];
__device__ int   g_esrc[1600000 + 1024];                    // src sorted by dst (CSR)
__device__ float g_inv[NMAX];
__device__ int   g_part[256];
__device__ int   g_pbase[256];
__device__ int   g_idx32;

// ---------------------------------------------------------------------------
__device__ __forceinline__ uint32_t smem_u32(const void* p) {
    uint32_t a;
    asm("{ .reg .u64 t; cvta.to.shared.u64 t, %1; cvt.u32.u64 %0, t; }" : "=r"(a) : "l"(p));
    return a;
}

__device__ __forceinline__ void cpasync16(uint32_t s, const void* g, int sz) {
    asm volatile("cp.async.cg.shared.global [%0], [%1], 16, %2;"
                 :: "r"(s), "l"(g), "r"(sz) : "memory");
}

#define LDSM4(r0, r1, r2, r3, addr)                                           \
    asm volatile("ldmatrix.sync.aligned.m8n8.x4.shared.b16 {%0,%1,%2,%3},[%4];" \
                 : "=r"(r0), "=r"(r1), "=r"(r2), "=r"(r3) : "r"(addr))

#define MMA_F16(c, a0, a1, a2, a3, b0, b1)                                    \
    asm volatile("mma.sync.aligned.m16n8k16.row.col.f32.f16.f16.f32 "         \
                 "{%0,%1,%2,%3},{%4,%5,%6,%7},{%8,%9},{%0,%1,%2,%3};"         \
                 : "+f"((c)[0]), "+f"((c)[1]), "+f"((c)[2]), "+f"((c)[3])     \
                 : "r"(a0), "r"(a1), "r"(a2), "r"(a3), "r"(b0), "r"(b1))

// ---------------------------------------------------------------------------
__global__ void detect_kernel(const void* eidx) {
    const ull* p = (const ull*)eidx;
    int is32 = 0;
    #pragma unroll
    for (int i = 0; i < 4; i++)
        if (p[i] >= (1ULL << 32)) is32 = 1;
    g_idx32 = is32;
}

__device__ __forceinline__ int load_idx(const void* eidx, long long pos) {
    if (g_idx32) return ((const int*)eidx)[pos];
    return (int)(((const long long*)eidx)[pos]);
}

// fp32 -> fp16 plane conversion.
__global__ void tohalf_kernel(const float4* __restrict__ src,
                              uint2* __restrict__ dst, int n4) {
    int t = blockIdx.x * blockDim.x + threadIdx.x;
    if (t >= n4) return;
    float4 v = src[t];
    __half2 h0 = __floats2half2_rn(v.x, v.y);
    __half2 h1 = __floats2half2_rn(v.z, v.w);
    dst[t] = make_uint2(*(uint32_t*)&h0, *(uint32_t*)&h1);
}

// fp16 weight image: [layer][kc][n][64 halves], B[n][k] = W[k][n].
// kc 0,1 = Wl (mean path) chunks; kc 2,3 = Wr (x path) chunks.
__global__ void wconv16_kernel(const float* __restrict__ Wl1, const float* __restrict__ Wr1,
                               const float* __restrict__ Wl2, const float* __restrict__ Wr2) {
    int unit = blockIdx.x * 256 + threadIdx.x;   // 1024 units
    if (unit >= 1024) return;
    int layer = unit >> 9;
    int kc = (unit >> 7) & 3;
    int n = unit & 127;
    const float* Wsrc = (layer == 0) ? ((kc < 2) ? Wl1 : Wr1)
                                     : ((kc < 2) ? Wl2 : Wr2);
    int kbase = (kc & 1) * 64;
    uint32_t buf[32];
    #pragma unroll
    for (int j = 0; j < 32; j++) {
        float v0 = Wsrc[(kbase + 2 * j) * 128 + n];
        float v1 = Wsrc[(kbase + 2 * j + 1) * 128 + n];
        __half2 h = __floats2half2_rn(v0, v1);
        buf[j] = *(uint32_t*)&h;
    }
    char* dst = g_W16 + (((size_t)layer * 4 + kc) * 128 + n) * 128;
    #pragma unroll
    for (int q = 0; q < 8; q++)
        ((uint4*)dst)[q] = make_uint4(buf[4 * q], buf[4 * q + 1],
                                      buf[4 * q + 2], buf[4 * q + 3]);
}

// 4 edges per thread, vectorized index loads.
__global__ void deg_kernel(const void* eidx, int nE) {
    int t = blockIdx.x * blockDim.x + threadIdx.x;
    int ngrp = nE >> 2;
    if (t < ngrp) {
        int d0, d1, d2, d3;
        if (g_idx32) {
            int4 v = ((const int4*)eidx)[ngrp + t];
            d0 = v.x; d1 = v.y; d2 = v.z; d3 = v.w;
        } else {
            longlong2 v0 = ((const longlong2*)eidx)[(nE >> 1) + t * 2];
            longlong2 v1 = ((const longlong2*)eidx)[(nE >> 1) + t * 2 + 1];
            d0 = (int)v0.x; d1 = (int)v0.y; d2 = (int)v1.x; d3 = (int)v1.y;
        }
        atomicAdd(&g_deg[d0], 1);
        atomicAdd(&g_deg[d1], 1);
        atomicAdd(&g_deg[d2], 1);
        atomicAdd(&g_deg[d3], 1);
    } else if (t == ngrp) {
        for (int e = ngrp * 4; e < nE; e++)
            atomicAdd(&g_deg[load_idx(eidx, (long long)nE + e)], 1);
    }
}

// Parallel 3-phase exclusive scan over degrees.
__global__ void blocksum_kernel(int nN) {
    __shared__ int ws[8];
    int t = threadIdx.x;
    int base = blockIdx.x * 1024 + t * 4;
    int s = 0;
    #pragma unroll
    for (int j = 0; j < 4; j++) {
        int i = base + j;
        if (i < nN) s += g_deg[i];
    }
    #pragma unroll
    for (int o = 16; o > 0; o >>= 1) s += __shfl_down_sync(~0u, s, o);
    if ((t & 31) == 0) ws[t >> 5] = s;
    __syncthreads();
    if (t < 8) {
        int v = ws[t];
        #pragma unroll
        for (int o = 4; o > 0; o >>= 1) v += __shfl_down_sync(0xff, v, o);
        if (t == 0) g_part[blockIdx.x] = v;
    }
}

__global__ void scanpart_kernel(int nb) {
    __shared__ int sm[128];
    int t = threadIdx.x;
    int v = (t < nb) ? g_part[t] : 0;
    sm[t] = v;
    __syncthreads();
    for (int o = 1; o < 128; o <<= 1) {
        int u = (t >= o) ? sm[t - o] : 0;
        __syncthreads();
        sm[t] += u;
        __syncthreads();
    }
    g_pbase[t] = (t == 0) ? 0 : sm[t - 1];
}

__global__ void offsets_kernel(int nN, int nE) {
    __shared__ int warp_tot[8];
    int t = threadIdx.x;
    int blk = blockIdx.x;
    int lane = t & 31, w = t >> 5;
    int base = blk * 1024 + t * 4;
    int d[4];
    int s = 0;
    #pragma unroll
    for (int j = 0; j < 4; j++) {
        int i = base + j;
        d[j] = (i < nN) ? g_deg[i] : 0;
        s += d[j];
    }
    int inc = s;
    #pragma unroll
    for (int o = 1; o < 32; o <<= 1) {
        int u = __shfl_up_sync(~0u, inc, o);
        if (lane >= o) inc += u;
    }
    if (lane == 31) warp_tot[w] = inc;
    __syncthreads();
    if (t < 8) {
        int v = warp_tot[t];
        #pragma unroll
        for (int o = 1; o < 8; o <<= 1) {
            int u = __shfl_up_sync(0xff, v, o);
            if (t >= o) v += u;
        }
        warp_tot[t] = v;
    }
    __syncthreads();
    int run = g_pbase[blk] + (inc - s) + ((w > 0) ? warp_tot[w - 1] : 0);
    #pragma unroll
    for (int j = 0; j < 4; j++) {
        int i = base + j;
        if (i < nN) {
            g_off[i] = run;
            g_cur[i] = run;
            g_inv[i] = 1.0f / (float)(d[j] > 0 ? d[j] : 1);
            run += d[j];
        }
    }
    if (blk == 0 && t == 0) g_off[nN] = nE;
}

__global__ void fill_kernel(const void* eidx, int nE) {
    int t = blockIdx.x * blockDim.x + threadIdx.x;
    int ngrp = nE >> 2;
    if (t < ngrp) {
        int s0, s1, s2, s3, d0, d1, d2, d3;
        if (g_idx32) {
            int4 sv = ((const int4*)eidx)[t];
            int4 dv = ((const int4*)eidx)[ngrp + t];
            s0 = sv.x; s1 = sv.y; s2 = sv.z; s3 = sv.w;
            d0 = dv.x; d1 = dv.y; d2 = dv.z; d3 = dv.w;
        } else {
            longlong2 a0 = ((const longlong2*)eidx)[t * 2];
            longlong2 a1 = ((const longlong2*)eidx)[t * 2 + 1];
            longlong2 b0 = ((const longlong2*)eidx)[(nE >> 1) + t * 2];
            longlong2 b1 = ((const longlong2*)eidx)[(nE >> 1) + t * 2 + 1];
            s0 = (int)a0.x; s1 = (int)a0.y; s2 = (int)a1.x; s3 = (int)a1.y;
            d0 = (int)b0.x; d1 = (int)b0.y; d2 = (int)b1.x; d3 = (int)b1.y;
        }
        g_esrc[atomicAdd(&g_cur[d0], 1)] = s0;
        g_esrc[atomicAdd(&g_cur[d1], 1)] = s1;
        g_esrc[atomicAdd(&g_cur[d2], 1)] = s2;
        g_esrc[atomicAdd(&g_cur[d3], 1)] = s3;
    } else if (t == ngrp) {
        for (int e = ngrp * 4; e < nE; e++) {
            int src = load_idx(eidx, e);
            int dst = load_idx(eidx, (long long)nE + e);
            g_esrc[atomicAdd(&g_cur[dst], 1)] = src;
        }
    }
}

// ---------------------------------------------------------------------------
__device__ __forceinline__ void acc4h(float4& a, uint2 v) {
    float2 p = __half22float2(*(__half2*)&v.x);
    float2 q = __half22float2(*(__half2*)&v.y);
    a.x += p.x; a.y += p.y; a.z += q.x; a.w += q.y;
}

// ---------------------------------------------------------------------------
// FUSED agg + fp16 mma.sync GEMM per layer.
//   out[128-tile,128] = concat(mean,x)[128,256] @ W16[256,128] + b
// In-CTA: gather means -> smem fp16 tiles; MMA chunk order [x0, x1, mean0,
// mean1] so x-MMAs run while gather/staging latency drains; 2 CTAs/SM overlap
// one CTA's gather (L2) with the other's MMA (tensor).
// SMEM slots (RS16=144 pad, ldmatrix conflict-free): mean0, mean1, ax0, ax1,
// b0, b1 -> 6 * 18432 = 110592 B.
#define RS16 144
#define TILE16 (128 * RS16)            // 18432
#define SLOT_M0 0
#define SLOT_M1 TILE16
#define SLOT_X0 (2 * TILE16)
#define SLOT_X1 (3 * TILE16)
#define SLOT_B0 (4 * TILE16)
#define SLOT_B1 (5 * TILE16)
#define SM_TOTAL (6 * TILE16)          // 110592, 2 CTAs/SM

template <bool RELU, bool EMIT16>
__global__ void __launch_bounds__(256, 2)
fused_kernel(const uint2* __restrict__ plane16, int layer,
             const float* __restrict__ bias,
             float* __restrict__ out, uint32_t* __restrict__ out16, int nN) {
    extern __shared__ char smem[];
    const uint32_t s0_u = smem_u32(smem);

    const int tid = threadIdx.x;
    const int wid = tid >> 5;
    const int lane = tid & 31;
    const int g = lane >> 2;
    const int tg = lane & 3;
    const int warp_m = wid & 3;     // rows warp_m*32..+31
    const int warp_n = wid >> 2;    // cols warp_n*64..+63
    const int m0 = blockIdx.x * 128;

    // per-lane ldmatrix offsets within a tile
    uint32_t offA[2];
    #pragma unroll
    for (int t = 0; t < 2; t++)
        offA[t] = (uint32_t)((warp_m * 32 + t * 16 + (lane & 7)
                   + ((lane >> 3) & 1) * 8) * RS16 + ((lane >> 4) & 1) * 16);
    uint32_t offB[4];
    #pragma unroll
    for (int up = 0; up < 4; up++)
        offB[up] = (uint32_t)((warp_n * 64 + up * 16 + (lane & 7)
                   + ((lane >> 4) & 1) * 8) * RS16 + ((lane >> 3) & 1) * 16);

    // stage one x chunk (64 k-cols) into a slot
    auto stageX = [&](uint32_t slot, int koffB) {
        #pragma unroll
        for (int it = 0; it < 4; it++) {
            int i = tid + it * 256;          // 0..1023
            int row = i >> 3, q = i & 7;
            int node = m0 + row;
            const char* gp = (const char*)plane16 + (size_t)node * 256 + koffB + q * 16;
            cpasync16(s0_u + slot + row * RS16 + q * 16, gp, (node < nN) ? 16 : 0);
        }
    };
    // stage one W chunk into a slot
    auto stageB = [&](uint32_t slot, int kc) {
        const char* wsrc = g_W16 + ((size_t)layer * 4 + kc) * 16384;
        #pragma unroll
        for (int it = 0; it < 4; it++) {
            int i = tid + it * 256;
            int n = i >> 3, q = i & 7;
            cpasync16(s0_u + slot + n * RS16 + q * 16, wsrc + n * 128 + q * 16, 16);
        }
    };

    float acc[2][8][4];
    #pragma unroll
    for (int t = 0; t < 2; t++)
        #pragma unroll
        for (int u = 0; u < 8; u++)
            #pragma unroll
            for (int c = 0; c < 4; c++) acc[t][u][c] = 0.f;

    auto mma_chunk = [&](uint32_t abase, uint32_t bbase) {
        #pragma unroll
        for (int ks = 0; ks < 4; ks++) {
            uint32_t a[2][4];
            LDSM4(a[0][0], a[0][1], a[0][2], a[0][3], s0_u + abase + offA[0] + ks * 32);
            LDSM4(a[1][0], a[1][1], a[1][2], a[1][3], s0_u + abase + offA[1] + ks * 32);
            uint32_t b[8][2];
            #pragma unroll
            for (int up = 0; up < 4; up++)
                LDSM4(b[2 * up][0], b[2 * up][1], b[2 * up + 1][0], b[2 * up + 1][1],
                      s0_u + bbase + offB[up] + ks * 32);
            #pragma unroll
            for (int u = 0; u < 8; u++)
                #pragma unroll
                for (int t = 0; t < 2; t++)
                    MMA_F16(acc[t][u], a[t][0], a[t][1], a[t][2], a[t][3],
                            b[u][0], b[u][1]);
        }
    };

    // ---- prologue: stage x chunks + first two B chunks (groups g0, g1) ----
    stageX(SLOT_X0, 0);   stageB(SLOT_B0, 2);
    asm volatile("cp.async.commit_group;" ::: "memory");   // g0
    stageX(SLOT_X1, 128); stageB(SLOT_B1, 3);
    asm volatile("cp.async.commit_group;" ::: "memory");   // g1

    // ---- gather: warp wid handles rows wid*16..+15; lane = 4 cols (8B) ----
    {
        int row0 = wid * 16;
        for (int j = 0; j < 16; j++) {
            int row = row0 + j;
            int node = m0 + row;
            float4 a0 = make_float4(0.f, 0.f, 0.f, 0.f);
            float4 a1 = a0;
            float inv = 0.f;
            if (node < nN) {
                int beg = g_off[node], end = g_off[node + 1];
                int i = beg;
                for (; i + 3 < end; i += 4) {
                    int s0 = g_esrc[i], s1 = g_esrc[i + 1];
                    int s2 = g_esrc[i + 2], s3 = g_esrc[i + 3];
                    uint2 v0 = plane16[(size_t)s0 * 32 + lane];
                    uint2 v1 = plane16[(size_t)s1 * 32 + lane];
                    uint2 v2 = plane16[(size_t)s2 * 32 + lane];
                    uint2 v3 = plane16[(size_t)s3 * 32 + lane];
                    acc4h(a0, v0); acc4h(a1, v1); acc4h(a0, v2); acc4h(a1, v3);
                }
                for (; i < end; i++) {
                    uint2 v0 = plane16[(size_t)g_esrc[i] * 32 + lane];
                    acc4h(a0, v0);
                }
                inv = g_inv[node];
            }
            __half2 o0 = __floats2half2_rn((a0.x + a1.x) * inv, (a0.y + a1.y) * inv);
            __half2 o1 = __floats2half2_rn((a0.z + a1.z) * inv, (a0.w + a1.w) * inv);
            uint32_t slot = (lane < 16) ? SLOT_M0 : SLOT_M1;
            *(uint2*)(smem + slot + row * RS16 + (lane & 15) * 8) =
                make_uint2(*(uint32_t*)&o0, *(uint32_t*)&o1);
        }
    }

    // ---- MMA pipeline: chunks [x0(kc2), x1(kc3), mean0(kc0), mean1(kc1)] ----
    asm volatile("cp.async.wait_group 1;" ::: "memory");   // g0 done
    __syncthreads();
    mma_chunk(SLOT_X0, SLOT_B0);
    __syncthreads();                                       // release B0
    stageB(SLOT_B0, 0);
    asm volatile("cp.async.commit_group;" ::: "memory");   // g2
    asm volatile("cp.async.wait_group 1;" ::: "memory");   // g1 done
    __syncthreads();
    mma_chunk(SLOT_X1, SLOT_B1);
    __syncthreads();                                       // release B1
    stageB(SLOT_B1, 1);
    asm volatile("cp.async.commit_group;" ::: "memory");   // g3
    asm volatile("cp.async.wait_group 1;" ::: "memory");   // g2 done
    __syncthreads();
    mma_chunk(SLOT_M0, SLOT_B0);
    asm volatile("cp.async.wait_group 0;" ::: "memory");   // g3 done
    __syncthreads();
    mma_chunk(SLOT_M1, SLOT_B1);

    // ---- epilogue ----
    #pragma unroll
    for (int u = 0; u < 8; u++) {
        int cb = warp_n * 64 + u * 8 + 2 * tg;
        float2 bv = *(const float2*)(bias + cb);
        #pragma unroll
        for (int t = 0; t < 2; t++) {
            int r0 = m0 + warp_m * 32 + t * 16 + g;
            float2 o0 = make_float2(acc[t][u][0] + bv.x, acc[t][u][1] + bv.y);
            float2 o1 = make_float2(acc[t][u][2] + bv.x, acc[t][u][3] + bv.y);
            if (RELU) {
                o0.x = fmaxf(o0.x, 0.f); o0.y = fmaxf(o0.y, 0.f);
                o1.x = fmaxf(o1.x, 0.f); o1.y = fmaxf(o1.y, 0.f);
            }
            if (EMIT16) {
                if (r0 < nN) {
                    __half2 p = __floats2half2_rn(o0.x, o0.y);
                    out16[(size_t)r0 * 64 + (cb >> 1)] = *(uint32_t*)&p;
                }
                if (r0 + 8 < nN) {
                    __half2 p = __floats2half2_rn(o1.x, o1.y);
                    out16[(size_t)(r0 + 8) * 64 + (cb >> 1)] = *(uint32_t*)&p;
                }
            } else {
                if (r0 < nN)     *(float2*)(out + (size_t)r0 * 128 + cb) = o0;
                if (r0 + 8 < nN) *(float2*)(out + (size_t)(r0 + 8) * 128 + cb) = o1;
            }
        }
    }
}

// ---------------------------------------------------------------------------
extern "C" void kernel_launch(void* const* d_in, const int* in_sizes, int n_in,
                              void* d_out, int out_size) {
    const float* x   = (const float*)d_in[0];
    const void*  eix = d_in[1];
    const float* Wl1 = (const float*)d_in[2];
    const float* Wr1 = (const float*)d_in[3];
    const float* b1  = (const float*)d_in[4];
    const float* Wl2 = (const float*)d_in[5];
    const float* Wr2 = (const float*)d_in[6];
    const float* b2  = (const float*)d_in[7];
    float* out = (float*)d_out;

    const int nN = in_sizes[0] / D;      // 100000
    const int nE = in_sizes[1] / 2;      // 1600000

    void *degp, *x16p, *h16p;
    cudaGetSymbolAddress(&degp, g_deg);
    cudaGetSymbolAddress(&x16p, g_x16);
    cudaGetSymbolAddress(&h16p, g_h16);

    cudaFuncSetAttribute(fused_kernel<true, true>,
                         cudaFuncAttributeMaxDynamicSharedMemorySize, SM_TOTAL);
    cudaFuncSetAttribute(fused_kernel<false, false>,
                         cudaFuncAttributeMaxDynamicSharedMemorySize, SM_TOTAL);

    const int edgeGrpBlocks = ((nE / 4 + 1) + 255) / 256;
    const int gemmBlocks = (nN + 127) / 128;
    const int scanBlocks = (nN + 1023) / 1024;    // 98
    const int n4 = nN * 32;
    const int convBlocks = (n4 + 255) / 256;

    // ---- CSR build + weight/x fp16 conversion ----
    cudaMemsetAsync(degp, 0, (size_t)nN * sizeof(int));
    detect_kernel<<<1, 1>>>(eix);
    wconv16_kernel<<<4, 256>>>(Wl1, Wr1, Wl2, Wr2);
    tohalf_kernel<<<convBlocks, 256>>>((const float4*)x, (uint2*)x16p, n4);
    deg_kernel<<<edgeGrpBlocks, 256>>>(eix, nE);
    blocksum_kernel<<<scanBlocks, 256>>>(nN);
    scanpart_kernel<<<1, 128>>>(scanBlocks);
    offsets_kernel<<<scanBlocks, 256>>>(nN, nE);
    fill_kernel<<<edgeGrpBlocks, 256>>>(eix, nE);

    // ---- layer 1 (fused agg+gemm; emits fp16 plane h16) ----
    fused_kernel<true, true><<<gemmBlocks, 256, SM_TOTAL>>>(
        (const uint2*)x16p, 0, b1, nullptr, (uint32_t*)h16p, nN);

    // ---- layer 2 (fused agg+gemm; fp32 output) ----
    fused_kernel<false, false><<<gemmBlocks, 256, SM_TOTAL>>>(
        (const uint2*)h16p, 1, b2, out, nullptr, nN);
}

// round 16
// speedup vs baseline: 2.2575x; 2.2575x over previous
#include <cuda_runtime.h>
#include <cuda_bf16.h>
#include <cuda_fp16.h>
#include <cstdint>

#define NMAX 100000
#define D 128

typedef unsigned long long ull;

// Scratch (device globals: allocation-free per harness rules)
__device__ __align__(256) uint2 g_x16[(size_t)NMAX * 32];   // fp16 plane of x
__device__ __align__(256) uint2 g_h16[(size_t)NMAX * 32];   // fp16 plane of h (layer-1 out)
__device__ __align__(256) uint2 g_agg16[(size_t)NMAX * 32]; // fp16 plane of mean-agg
__device__ __align__(16)  char  g_W16[131072];              // fp16 weights [layer][kc][n][64]
__device__ int   g_deg[NMAX];
__device__ int   g_off[NMAX + 1];
__device__ int   g_cur[NMAX];
__device__ int   g_esrc[1600000 + 1024];                    // src sorted by dst (CSR)
__device__ float g_inv[NMAX];
__device__ int   g_part[256];
__device__ int   g_pbase[256];
__device__ int   g_idx32;

// ---------------------------------------------------------------------------
__device__ __forceinline__ uint32_t smem_u32(const void* p) {
    uint32_t a;
    asm("{ .reg .u64 t; cvta.to.shared.u64 t, %1; cvt.u32.u64 %0, t; }" : "=r"(a) : "l"(p));
    return a;
}

__device__ __forceinline__ void cpasync16(uint32_t s, const void* g, int sz) {
    asm volatile("cp.async.cg.shared.global [%0], [%1], 16, %2;"
                 :: "r"(s), "l"(g), "r"(sz) : "memory");
}

#define LDSM4(r0, r1, r2, r3, addr)                                           \
    asm volatile("ldmatrix.sync.aligned.m8n8.x4.shared.b16 {%0,%1,%2,%3},[%4];" \
                 : "=r"(r0), "=r"(r1), "=r"(r2), "=r"(r3) : "r"(addr))

#define MMA_F16(c, a0, a1, a2, a3, b0, b1)                                    \
    asm volatile("mma.sync.aligned.m16n8k16.row.col.f32.f16.f16.f32 "         \
                 "{%0,%1,%2,%3},{%4,%5,%6,%7},{%8,%9},{%0,%1,%2,%3};"         \
                 : "+f"((c)[0]), "+f"((c)[1]), "+f"((c)[2]), "+f"((c)[3])     \
                 : "r"(a0), "r"(a1), "r"(a2), "r"(a3), "r"(b0), "r"(b1))

// ---------------------------------------------------------------------------
__global__ void detect_kernel(const void* eidx) {
    const ull* p = (const ull*)eidx;
    int is32 = 0;
    #pragma unroll
    for (int i = 0; i < 4; i++)
        if (p[i] >= (1ULL << 32)) is32 = 1;
    g_idx32 = is32;
}

__device__ __forceinline__ int load_idx(const void* eidx, long long pos) {
    if (g_idx32) return ((const int*)eidx)[pos];
    return (int)(((const long long*)eidx)[pos]);
}

// fp32 -> fp16 plane conversion.
__global__ void tohalf_kernel(const float4* __restrict__ src,
                              uint2* __restrict__ dst, int n4) {
    int t = blockIdx.x * blockDim.x + threadIdx.x;
    if (t >= n4) return;
    float4 v = src[t];
    __half2 h0 = __floats2half2_rn(v.x, v.y);
    __half2 h1 = __floats2half2_rn(v.z, v.w);
    dst[t] = make_uint2(*(uint32_t*)&h0, *(uint32_t*)&h1);
}

// fp16 weight image: [layer][kc][n][64 halves], B[n][k] = W[k][n].
__global__ void wconv16_kernel(const float* __restrict__ Wl1, const float* __restrict__ Wr1,
                               const float* __restrict__ Wl2, const float* __restrict__ Wr2) {
    int unit = blockIdx.x * 256 + threadIdx.x;   // 1024 units
    if (unit >= 1024) return;
    int layer = unit >> 9;
    int kc = (unit >> 7) & 3;
    int n = unit & 127;
    const float* Wsrc = (layer == 0) ? ((kc < 2) ? Wl1 : Wr1)
                                     : ((kc < 2) ? Wl2 : Wr2);
    int kbase = (kc & 1) * 64;
    uint32_t buf[32];
    #pragma unroll
    for (int j = 0; j < 32; j++) {
        float v0 = Wsrc[(kbase + 2 * j) * 128 + n];
        float v1 = Wsrc[(kbase + 2 * j + 1) * 128 + n];
        __half2 h = __floats2half2_rn(v0, v1);
        buf[j] = *(uint32_t*)&h;
    }
    char* dst = g_W16 + (((size_t)layer * 4 + kc) * 128 + n) * 128;
    #pragma unroll
    for (int q = 0; q < 8; q++)
        ((uint4*)dst)[q] = make_uint4(buf[4 * q], buf[4 * q + 1],
                                      buf[4 * q + 2], buf[4 * q + 3]);
}

// 8 edges per thread, two independent vector index loads (2x MLP vs R13).
__global__ void deg_kernel(const void* eidx, int nE) {
    int t = blockIdx.x * blockDim.x + threadIdx.x;
    int ngrp = nE >> 3;
    if (t < ngrp) {
        int d[8];
        if (g_idx32) {
            const int4* base = (const int4*)eidx + (nE >> 2);
            int4 v0 = base[t * 2];
            int4 v1 = base[t * 2 + 1];
            d[0] = v0.x; d[1] = v0.y; d[2] = v0.z; d[3] = v0.w;
            d[4] = v1.x; d[5] = v1.y; d[6] = v1.z; d[7] = v1.w;
        } else {
            const longlong2* base = (const longlong2*)eidx + (nE >> 1);
            longlong2 v0 = base[t * 4];
            longlong2 v1 = base[t * 4 + 1];
            longlong2 v2 = base[t * 4 + 2];
            longlong2 v3 = base[t * 4 + 3];
            d[0] = (int)v0.x; d[1] = (int)v0.y; d[2] = (int)v1.x; d[3] = (int)v1.y;
            d[4] = (int)v2.x; d[5] = (int)v2.y; d[6] = (int)v3.x; d[7] = (int)v3.y;
        }
        #pragma unroll
        for (int j = 0; j < 8; j++) atomicAdd(&g_deg[d[j]], 1);
    } else if (t == ngrp) {
        for (int e = ngrp * 8; e < nE; e++)
            atomicAdd(&g_deg[load_idx(eidx, (long long)nE + e)], 1);
    }
}

// Parallel 3-phase exclusive scan over degrees.
__global__ void blocksum_kernel(int nN) {
    __shared__ int ws[8];
    int t = threadIdx.x;
    int base = blockIdx.x * 1024 + t * 4;
    int s = 0;
    #pragma unroll
    for (int j = 0; j < 4; j++) {
        int i = base + j;
        if (i < nN) s += g_deg[i];
    }
    #pragma unroll
    for (int o = 16; o > 0; o >>= 1) s += __shfl_down_sync(~0u, s, o);
    if ((t & 31) == 0) ws[t >> 5] = s;
    __syncthreads();
    if (t < 8) {
        int v = ws[t];
        #pragma unroll
        for (int o = 4; o > 0; o >>= 1) v += __shfl_down_sync(0xff, v, o);
        if (t == 0) g_part[blockIdx.x] = v;
    }
}

__global__ void scanpart_kernel(int nb) {
    __shared__ int sm[128];
    int t = threadIdx.x;
    int v = (t < nb) ? g_part[t] : 0;
    sm[t] = v;
    __syncthreads();
    for (int o = 1; o < 128; o <<= 1) {
        int u = (t >= o) ? sm[t - o] : 0;
        __syncthreads();
        sm[t] += u;
        __syncthreads();
    }
    g_pbase[t] = (t == 0) ? 0 : sm[t - 1];
}

__global__ void offsets_kernel(int nN, int nE) {
    __shared__ int warp_tot[8];
    int t = threadIdx.x;
    int blk = blockIdx.x;
    int lane = t & 31, w = t >> 5;
    int base = blk * 1024 + t * 4;
    int d[4];
    int s = 0;
    #pragma unroll
    for (int j = 0; j < 4; j++) {
        int i = base + j;
        d[j] = (i < nN) ? g_deg[i] : 0;
        s += d[j];
    }
    int inc = s;
    #pragma unroll
    for (int o = 1; o < 32; o <<= 1) {
        int u = __shfl_up_sync(~0u, inc, o);
        if (lane >= o) inc += u;
    }
    if (lane == 31) warp_tot[w] = inc;
    __syncthreads();
    if (t < 8) {
        int v = warp_tot[t];
        #pragma unroll
        for (int o = 1; o < 8; o <<= 1) {
            int u = __shfl_up_sync(0xff, v, o);
            if (t >= o) v += u;
        }
        warp_tot[t] = v;
    }
    __syncthreads();
    int run = g_pbase[blk] + (inc - s) + ((w > 0) ? warp_tot[w - 1] : 0);
    #pragma unroll
    for (int j = 0; j < 4; j++) {
        int i = base + j;
        if (i < nN) {
            g_off[i] = run;
            g_cur[i] = run;
            g_inv[i] = 1.0f / (float)(d[j] > 0 ? d[j] : 1);
            run += d[j];
        }
    }
    if (blk == 0 && t == 0) g_off[nN] = nE;
}

// 8 edges per thread, two independent vector loads for src and dst.
__global__ void fill_kernel(const void* eidx, int nE) {
    int t = blockIdx.x * blockDim.x + threadIdx.x;
    int ngrp = nE >> 3;
    if (t < ngrp) {
        int s[8], d[8];
        if (g_idx32) {
            const int4* sb = (const int4*)eidx;
            const int4* db = sb + (nE >> 2);
            int4 sv0 = sb[t * 2], sv1 = sb[t * 2 + 1];
            int4 dv0 = db[t * 2], dv1 = db[t * 2 + 1];
            s[0] = sv0.x; s[1] = sv0.y; s[2] = sv0.z; s[3] = sv0.w;
            s[4] = sv1.x; s[5] = sv1.y; s[6] = sv1.z; s[7] = sv1.w;
            d[0] = dv0.x; d[1] = dv0.y; d[2] = dv0.z; d[3] = dv0.w;
            d[4] = dv1.x; d[5] = dv1.y; d[6] = dv1.z; d[7] = dv1.w;
        } else {
            const longlong2* sb = (const longlong2*)eidx;
            const longlong2* db = sb + (nE >> 1);
            #pragma unroll
            for (int q = 0; q < 4; q++) {
                longlong2 sv = sb[t * 4 + q];
                longlong2 dv = db[t * 4 + q];
                s[2 * q] = (int)sv.x; s[2 * q + 1] = (int)sv.y;
                d[2 * q] = (int)dv.x; d[2 * q + 1] = (int)dv.y;
            }
        }
        #pragma unroll
        for (int j = 0; j < 8; j++)
            g_esrc[atomicAdd(&g_cur[d[j]], 1)] = s[j];
    } else if (t == ngrp) {
        for (int e = ngrp * 8; e < nE; e++) {
            int src = load_idx(eidx, e);
            int dst = load_idx(eidx, (long long)nE + e);
            g_esrc[atomicAdd(&g_cur[dst], 1)] = src;
        }
    }
}

// ---------------------------------------------------------------------------
// fp16-plane gather aggregation; fp32 accum; writes fp16 mean plane.
__device__ __forceinline__ void acc4h(float4& a, uint2 v) {
    float2 p = __half22float2(*(__half2*)&v.x);
    float2 q = __half22float2(*(__half2*)&v.y);
    a.x += p.x; a.y += p.y; a.z += q.x; a.w += q.y;
}

__global__ void agg16_kernel(const uint2* __restrict__ f16, int nN) {
    int gtid = blockIdx.x * blockDim.x + threadIdx.x;
    int w = gtid >> 5;
    int lane = gtid & 31;
    if (w >= nN) return;
    int beg = g_off[w], end = g_off[w + 1];
    float4 a0 = make_float4(0.f, 0.f, 0.f, 0.f);
    float4 a1 = a0;
    int i = beg;
    for (; i + 3 < end; i += 4) {
        int s0 = g_esrc[i], s1 = g_esrc[i + 1];
        int s2 = g_esrc[i + 2], s3 = g_esrc[i + 3];
        uint2 v0 = f16[(size_t)s0 * 32 + lane];
        uint2 v1 = f16[(size_t)s1 * 32 + lane];
        uint2 v2 = f16[(size_t)s2 * 32 + lane];
        uint2 v3 = f16[(size_t)s3 * 32 + lane];
        acc4h(a0, v0); acc4h(a1, v1); acc4h(a0, v2); acc4h(a1, v3);
    }
    for (; i < end; i++) {
        uint2 v0 = f16[(size_t)g_esrc[i] * 32 + lane];
        acc4h(a0, v0);
    }
    float inv = g_inv[w];
    __half2 o0 = __floats2half2_rn((a0.x + a1.x) * inv, (a0.y + a1.y) * inv);
    __half2 o1 = __floats2half2_rn((a0.z + a1.z) * inv, (a0.w + a1.w) * inv);
    g_agg16[(size_t)w * 32 + lane] = make_uint2(*(uint32_t*)&o0, *(uint32_t*)&o1);
}

// ---------------------------------------------------------------------------
// fp16 mma.sync GEMM, double-buffered (R13 — best known).
#define RS16 144
#define TILE16 (128 * RS16)            // 18432
#define BUF16 (2 * TILE16)             // A+B one stage
#define SM_TOTAL (2 * BUF16)           // 73728, 2 CTAs/SM

template <bool RELU, bool EMIT16>
__global__ void __launch_bounds__(256, 2)
gemm_f16_kernel(const uint2* __restrict__ xs16, int layer,
                const float* __restrict__ bias,
                float* __restrict__ out, uint32_t* __restrict__ out16, int nN) {
    extern __shared__ char smem[];
    const uint32_t s0_u = smem_u32(smem);

    const int tid = threadIdx.x;
    const int wid = tid >> 5;
    const int lane = tid & 31;
    const int g = lane >> 2;
    const int tg = lane & 3;
    const int warp_m = wid & 3;     // rows warp_m*32..+31
    const int warp_n = wid >> 2;    // cols warp_n*64..+63
    const int m0 = blockIdx.x * 128;

    uint32_t offA[2];
    #pragma unroll
    for (int t = 0; t < 2; t++)
        offA[t] = (uint32_t)((warp_m * 32 + t * 16 + (lane & 7)
                   + ((lane >> 3) & 1) * 8) * RS16 + ((lane >> 4) & 1) * 16);
    uint32_t offB[4];
    #pragma unroll
    for (int up = 0; up < 4; up++)
        offB[up] = (uint32_t)(TILE16 + (warp_n * 64 + up * 16 + (lane & 7)
                   + ((lane >> 4) & 1) * 8) * RS16 + ((lane >> 3) & 1) * 16);

    auto stage = [&](int kc) {
        const uint32_t base = s0_u + (kc & 1) * BUF16;
        const char* a16 = (const char*)((kc < 2) ? g_agg16 : xs16);
        const int koffB = (kc & 1) * 128;
        #pragma unroll
        for (int it = 0; it < 4; it++) {
            int i = tid + it * 256;
            int row = i >> 3, q = i & 7;
            int node = m0 + row;
            const char* gp = a16 + (size_t)node * 256 + koffB + q * 16;
            cpasync16(base + row * RS16 + q * 16, gp, (node < nN) ? 16 : 0);
        }
        const char* wsrc = g_W16 + ((size_t)layer * 4 + kc) * 16384;
        #pragma unroll
        for (int it = 0; it < 4; it++) {
            int i = tid + it * 256;
            int n = i >> 3, q = i & 7;
            cpasync16(base + TILE16 + n * RS16 + q * 16, wsrc + n * 128 + q * 16, 16);
        }
        asm volatile("cp.async.commit_group;" ::: "memory");
    };

    float acc[2][8][4];
    #pragma unroll
    for (int t = 0; t < 2; t++)
        #pragma unroll
        for (int u = 0; u < 8; u++)
            #pragma unroll
            for (int c = 0; c < 4; c++) acc[t][u][c] = 0.f;

    stage(0);
    #pragma unroll 1
    for (int kc = 0; kc < 4; kc++) {
        if (kc < 3) stage(kc + 1);
        if (kc < 3)
            asm volatile("cp.async.wait_group 1;" ::: "memory");
        else
            asm volatile("cp.async.wait_group 0;" ::: "memory");
        __syncthreads();
        const uint32_t base = s0_u + (kc & 1) * BUF16;
        #pragma unroll
        for (int ks = 0; ks < 4; ks++) {
            uint32_t a[2][4];
            LDSM4(a[0][0], a[0][1], a[0][2], a[0][3], base + offA[0] + ks * 32);
            LDSM4(a[1][0], a[1][1], a[1][2], a[1][3], base + offA[1] + ks * 32);
            uint32_t b[8][2];
            #pragma unroll
            for (int up = 0; up < 4; up++)
                LDSM4(b[2 * up][0], b[2 * up][1], b[2 * up + 1][0], b[2 * up + 1][1],
                      base + offB[up] + ks * 32);
            #pragma unroll
            for (int u = 0; u < 8; u++)
                #pragma unroll
                for (int t = 0; t < 2; t++)
                    MMA_F16(acc[t][u], a[t][0], a[t][1], a[t][2], a[t][3],
                            b[u][0], b[u][1]);
        }
        __syncthreads();
    }

    // ---- epilogue ----
    #pragma unroll
    for (int u = 0; u < 8; u++) {
        int cb = warp_n * 64 + u * 8 + 2 * tg;
        float2 bv = *(const float2*)(bias + cb);
        #pragma unroll
        for (int t = 0; t < 2; t++) {
            int r0 = m0 + warp_m * 32 + t * 16 + g;
            float2 o0 = make_float2(acc[t][u][0] + bv.x, acc[t][u][1] + bv.y);
            float2 o1 = make_float2(acc[t][u][2] + bv.x, acc[t][u][3] + bv.y);
            if (RELU) {
                o0.x = fmaxf(o0.x, 0.f); o0.y = fmaxf(o0.y, 0.f);
                o1.x = fmaxf(o1.x, 0.f); o1.y = fmaxf(o1.y, 0.f);
            }
            if (EMIT16) {
                if (r0 < nN) {
                    __half2 p = __floats2half2_rn(o0.x, o0.y);
                    out16[(size_t)r0 * 64 + (cb >> 1)] = *(uint32_t*)&p;
                }
                if (r0 + 8 < nN) {
                    __half2 p = __floats2half2_rn(o1.x, o1.y);
                    out16[(size_t)(r0 + 8) * 64 + (cb >> 1)] = *(uint32_t*)&p;
                }
            } else {
                if (r0 < nN)     *(float2*)(out + (size_t)r0 * 128 + cb) = o0;
                if (r0 + 8 < nN) *(float2*)(out + (size_t)(r0 + 8) * 128 + cb) = o1;
            }
        }
    }
}

// ---------------------------------------------------------------------------
extern "C" void kernel_launch(void* const* d_in, const int* in_sizes, int n_in,
                              void* d_out, int out_size) {
    const float* x   = (const float*)d_in[0];
    const void*  eix = d_in[1];
    const float* Wl1 = (const float*)d_in[2];
    const float* Wr1 = (const float*)d_in[3];
    const float* b1  = (const float*)d_in[4];
    const float* Wl2 = (const float*)d_in[5];
    const float* Wr2 = (const float*)d_in[6];
    const float* b2  = (const float*)d_in[7];
    float* out = (float*)d_out;

    const int nN = in_sizes[0] / D;      // 100000
    const int nE = in_sizes[1] / 2;      // 1600000

    void *degp, *x16p, *h16p;
    cudaGetSymbolAddress(&degp, g_deg);
    cudaGetSymbolAddress(&x16p, g_x16);
    cudaGetSymbolAddress(&h16p, g_h16);

    cudaFuncSetAttribute(gemm_f16_kernel<true, true>,
                         cudaFuncAttributeMaxDynamicSharedMemorySize, SM_TOTAL);
    cudaFuncSetAttribute(gemm_f16_kernel<false, false>,
                         cudaFuncAttributeMaxDynamicSharedMemorySize, SM_TOTAL);

    const int edgeGrpBlocks = ((nE / 8 + 1) + 255) / 256;
    const int aggBlocks  = (int)(((long long)nN * 32 + 255) / 256);
    const int gemmBlocks = (nN + 127) / 128;
    const int scanBlocks = (nN + 1023) / 1024;    // 98
    const int n4 = nN * 32;
    const int convBlocks = (n4 + 255) / 256;

    // ---- CSR build + weight/x fp16 conversion ----
    cudaMemsetAsync(degp, 0, (size_t)nN * sizeof(int));
    detect_kernel<<<1, 1>>>(eix);
    wconv16_kernel<<<4, 256>>>(Wl1, Wr1, Wl2, Wr2);
    tohalf_kernel<<<convBlocks, 256>>>((const float4*)x, (uint2*)x16p, n4);
    deg_kernel<<<edgeGrpBlocks, 256>>>(eix, nE);
    blocksum_kernel<<<scanBlocks, 256>>>(nN);
    scanpart_kernel<<<1, 128>>>(scanBlocks);
    offsets_kernel<<<scanBlocks, 256>>>(nN, nE);
    fill_kernel<<<edgeGrpBlocks, 256>>>(eix, nE);

    // ---- layer 1: emits only the fp16 plane h16 ----
    agg16_kernel<<<aggBlocks, 256>>>((const uint2*)x16p, nN);
    gemm_f16_kernel<true, true><<<gemmBlocks, 256, SM_TOTAL>>>(
        (const uint2*)x16p, 0, b1, nullptr, (uint32_t*)h16p, nN);

    // ---- layer 2: fp32 output ----
    agg16_kernel<<<aggBlocks, 256>>>((const uint2*)h16p, nN);
    gemm_f16_kernel<false, false><<<gemmBlocks, 256, SM_TOTAL>>>(
        (const uint2*)h16p, 1, b2, out, nullptr, nN);
}